// round 8
// baseline (speedup 1.0000x reference)
#include <cuda_runtime.h>
#include <cuda_bf16.h>
#include <cuda_fp16.h>

// Problem sizes (fixed by the reference: B=4, L=512, D=256)
#define B 4
#define L 512
#define D 256
#define D2 (D/2)              // 128 half2 pairs
#define R_SIZE (B*L*D)        // 524288 floats (r)
#define A_SIZE (B*L*L)        // 1048576 floats (alpha)

#define TILE 64               // i/j tile for scores kernel
#define NT   (L/TILE)         // 8 tiles per dim
#define NPAIR (NT*(NT+1)/2)   // 36 upper-tri tile pairs per batch
#define SH2  130              // half2 row stride (round-6 proven layout)

// 4 MB scratch for the pre-softmax scores
__device__ float g_scores[B*L*L];

__device__ __forceinline__ __half2 tanh2_approx(__half2 x) {
    unsigned xin = *reinterpret_cast<unsigned*>(&x);
    unsigned yout;
    asm("tanh.approx.f16x2 %0, %1;" : "=r"(yout) : "r"(xin));
    return *reinterpret_cast<__half2*>(&yout);
}

// ---------------------------------------------------------------------------
// Kernel 1 (EXACT round-6 version, measured 38.9us = MUFU pipe wall):
// scores[b,i,j] = sum_d tanh(H[b,i,d]+H[b,j,d])*w[d]  (bias dropped: softmax
// shift-invariant). Upper-triangle 64x64 tiles, mirrored on write.
// ---------------------------------------------------------------------------
__global__ void __launch_bounds__(512)
scores_kernel(const float* __restrict__ H,
              const float* __restrict__ w) {
    extern __shared__ __align__(16) unsigned smraw[];
    __half2* sHi = reinterpret_cast<__half2*>(smraw);           // 64 * SH2
    __half2* sHj = sHi + 64 * SH2;                              // 64 * SH2
    __half2* sWh = sHj + 64 * SH2;                              // D2

    const int blk = blockIdx.x;
    const int b   = blk / NPAIR;
    int p = blk % NPAIR;
    int ti = 0, rowlen = NT;
    while (p >= rowlen) { p -= rowlen; ++ti; --rowlen; }
    const int tj = ti + p;
    const int i0 = ti * TILE;
    const int j0 = tj * TILE;

    const int tid = threadIdx.x;
    const float* Hb = H + (size_t)b * L * D;

    if (tid < D2) {
        float2 wv = reinterpret_cast<const float2*>(w)[tid];
        sWh[tid] = __float22half2_rn(wv);
    }

    #pragma unroll
    for (int it = 0; it < 8; ++it) {
        int e = tid + 512 * it;
        int row = e >> 6;
        int c4  = e & 63;
        float4 v = *reinterpret_cast<const float4*>(Hb + (size_t)(i0 + row) * D + 4 * c4);
        sHi[row * SH2 + 2 * c4]     = __floats2half2_rn(v.x, v.y);
        sHi[row * SH2 + 2 * c4 + 1] = __floats2half2_rn(v.z, v.w);
    }
    #pragma unroll
    for (int it = 0; it < 8; ++it) {
        int e = tid + 512 * it;
        int row = e >> 6;
        int c4  = e & 63;
        float4 v = *reinterpret_cast<const float4*>(Hb + (size_t)(j0 + row) * D + 4 * c4);
        sHj[row * SH2 + 2 * c4]     = __floats2half2_rn(v.x, v.y);
        sHj[row * SH2 + 2 * c4 + 1] = __floats2half2_rn(v.z, v.w);
    }
    __syncthreads();

    const int tx = tid & 15;
    const int ty = tid >> 4;

    float accf[2][4];
    #pragma unroll
    for (int m = 0; m < 2; ++m)
        #pragma unroll
        for (int n = 0; n < 4; ++n) accf[m][n] = 0.0f;

    #pragma unroll 2
    for (int c = 0; c < D2 / 4; ++c) {
        __half2 acc2[2][4];
        #pragma unroll
        for (int m = 0; m < 2; ++m)
            #pragma unroll
            for (int n = 0; n < 4; ++n)
                acc2[m][n] = __halves2half2(__ushort_as_half(0), __ushort_as_half(0));

        #pragma unroll
        for (int u = 0; u < 4; ++u) {
            const int dp = 4 * c + u;
            const __half2 w2 = sWh[dp];
            __half2 hi[2], hj[4];
            #pragma unroll
            for (int m = 0; m < 2; ++m) hi[m] = sHi[(ty + 32 * m) * SH2 + dp];
            #pragma unroll
            for (int n = 0; n < 4; ++n) hj[n] = sHj[(tx + 16 * n) * SH2 + dp];
            #pragma unroll
            for (int m = 0; m < 2; ++m)
                #pragma unroll
                for (int n = 0; n < 4; ++n) {
                    __half2 t = tanh2_approx(__hadd2(hi[m], hj[n]));
                    acc2[m][n] = __hfma2(t, w2, acc2[m][n]);
                }
        }

        #pragma unroll
        for (int m = 0; m < 2; ++m)
            #pragma unroll
            for (int n = 0; n < 4; ++n) {
                float2 f = __half22float2(acc2[m][n]);
                accf[m][n] += f.x + f.y;
            }
    }

    const int mirror = (ti != tj);
    #pragma unroll
    for (int m = 0; m < 2; ++m) {
        int gi = i0 + ty + 32 * m;
        #pragma unroll
        for (int n = 0; n < 4; ++n) {
            int gj = j0 + tx + 16 * n;
            float v = accf[m][n];
            g_scores[((size_t)b * L + gi) * L + gj] = v;
            if (mirror)
                g_scores[((size_t)b * L + gj) * L + gi] = v;
        }
    }
}

// ---------------------------------------------------------------------------
// Kernel 2: fused softmax + GEMM, occupancy-aware.
// CTA = (b, 16 i-rows, 128 d-cols). Grid (2, 32, 4) = 256 CTAs, 128 threads,
// ~67KB smem -> 3 CTAs/SM -> ALL CTAs resident in one wave.
//   1) stage scores[16x512] in smem (stride 516)
//   2) in-place softmax numerators (8 lanes/row, interleaved cols -> no bank
//      conflicts); invS[16] per row
//   3) d-block-0 CTAs write alpha
//   4) GEMM 16x512 @ 512x128 out of smem A (no k-staging for A), B (H slice)
//      double-buffered; invS folded into epilogue.
// Per thread: 4 rows x 4 cols micro-tile (FMA-bound; crossbar < fma).
// ---------------------------------------------------------------------------
#define SSTR 516   // scores row stride (floats)
#define BSTR 132   // B tile row stride (floats)

__global__ void __launch_bounds__(128)
fused_softmax_gemm(const float* __restrict__ H,
                   float* __restrict__ out_alpha,
                   float* __restrict__ out_r) {
    extern __shared__ float fsm[];
    float* S    = fsm;                    // 16 * SSTR = 8256
    float* Bs   = fsm + 16 * SSTR;        // 2 * 32 * BSTR = 8448
    float* invS = Bs + 2 * 32 * BSTR;     // 16

    const int bx = blockIdx.x;            // d-block: 0 or 1
    const int i0 = blockIdx.y * 16;
    const int b  = blockIdx.z;
    const int d0 = bx * 128;
    const int tid = threadIdx.x;

    const float* Hb = H + (size_t)b * L * D;
    const float* Sg = g_scores + ((size_t)b * L + i0) * L;

    // Phase 1: scores block -> smem (16x512 = 2048 float4)
    #pragma unroll
    for (int it = 0; it < 16; ++it) {
        int e = tid + 128 * it;
        int row = e >> 7, c4 = e & 127;
        float4 v = *reinterpret_cast<const float4*>(Sg + (size_t)row * L + 4 * c4);
        *reinterpret_cast<float4*>(S + row * SSTR + 4 * c4) = v;
    }
    // Prologue: B tile 0 (k rows 0..31, 128 cols = 1024 float4)
    #pragma unroll
    for (int t = 0; t < 8; ++t) {
        int e = tid + 128 * t;
        int bk = e >> 5, c4 = e & 31;
        float4 v = *reinterpret_cast<const float4*>(Hb + (size_t)bk * D + d0 + 4 * c4);
        *reinterpret_cast<float4*>(Bs + bk * BSTR + 4 * c4) = v;
    }
    __syncthreads();

    // Phase 2: softmax numerators. 8 lanes/row; thread owns float4s at
    // column indices c4 = sub + 8*t (interleaved -> conflict-free LDS.128).
    {
        const int row = tid >> 3, sub = tid & 7;
        float* Srow = S + row * SSTR;

        float mx = -1e30f;
        #pragma unroll
        for (int t = 0; t < 16; ++t) {
            float4 v = *reinterpret_cast<const float4*>(Srow + 4 * (sub + 8 * t));
            mx = fmaxf(mx, fmaxf(fmaxf(v.x, v.y), fmaxf(v.z, v.w)));
        }
        #pragma unroll
        for (int o = 4; o; o >>= 1)
            mx = fmaxf(mx, __shfl_xor_sync(0xffffffffu, mx, o, 8));

        float s = 0.0f;
        #pragma unroll
        for (int t = 0; t < 16; ++t) {
            float4* p = reinterpret_cast<float4*>(Srow + 4 * (sub + 8 * t));
            float4 v = *p;
            v.x = __expf(v.x - mx); v.y = __expf(v.y - mx);
            v.z = __expf(v.z - mx); v.w = __expf(v.w - mx);
            s += (v.x + v.y) + (v.z + v.w);
            *p = v;
        }
        #pragma unroll
        for (int o = 4; o; o >>= 1)
            s += __shfl_xor_sync(0xffffffffu, s, o, 8);
        if (sub == 0) invS[row] = 1.0f / s;
    }
    __syncthreads();

    // Phase 3: alpha output (d-block 0 only)
    if (bx == 0) {
        const int row = tid >> 3, sub = tid & 7;
        const float is = invS[row];
        const float* Srow = S + row * SSTR;
        float* Arow = out_alpha + ((size_t)b * L + i0 + row) * L;
        #pragma unroll
        for (int t = 0; t < 16; ++t) {
            int c4 = sub + 8 * t;
            float4 v = *reinterpret_cast<const float4*>(Srow + 4 * c4);
            v.x *= is; v.y *= is; v.z *= is; v.w *= is;
            *reinterpret_cast<float4*>(Arow + 4 * c4) = v;
        }
    }

    // Phase 4: GEMM r[16x128] = S(16x512) @ H(512x128), A from smem directly.
    const int tx = tid & 31;              // col group: cols 4*tx .. 4*tx+3
    const int ty = tid >> 5;              // row group: rows 4*ty .. 4*ty+3

    float acc[4][4];
    #pragma unroll
    for (int m = 0; m < 4; ++m)
        #pragma unroll
        for (int n = 0; n < 4; ++n) acc[m][n] = 0.0f;

    #pragma unroll 1
    for (int kt = 0; kt < 16; ++kt) {
        const int cur = kt & 1, nxt = cur ^ 1;

        float4 pb[8];
        if (kt < 15) {
            const int k0n = (kt + 1) * 32;
            #pragma unroll
            for (int t = 0; t < 8; ++t) {
                int e = tid + 128 * t;
                int bk = e >> 5, c4 = e & 31;
                pb[t] = *reinterpret_cast<const float4*>(Hb + (size_t)(k0n + bk) * D + d0 + 4 * c4);
            }
        }

        const float* Bc = Bs + cur * 32 * BSTR;
        const int kb = kt * 32;
        #pragma unroll
        for (int kc = 0; kc < 8; ++kc) {
            float4 a4[4];
            #pragma unroll
            for (int r = 0; r < 4; ++r)
                a4[r] = *reinterpret_cast<const float4*>(S + (4 * ty + r) * SSTR + kb + 4 * kc);
            float4 bq[4];
            #pragma unroll
            for (int kk = 0; kk < 4; ++kk)
                bq[kk] = *reinterpret_cast<const float4*>(Bc + (4 * kc + kk) * BSTR + 4 * tx);
            #pragma unroll
            for (int kk = 0; kk < 4; ++kk) {
                #pragma unroll
                for (int r = 0; r < 4; ++r) {
                    const float av = reinterpret_cast<const float*>(&a4[r])[kk];
                    acc[r][0] = fmaf(av, bq[kk].x, acc[r][0]);
                    acc[r][1] = fmaf(av, bq[kk].y, acc[r][1]);
                    acc[r][2] = fmaf(av, bq[kk].z, acc[r][2]);
                    acc[r][3] = fmaf(av, bq[kk].w, acc[r][3]);
                }
            }
        }

        if (kt < 15) {
            float* Bn = Bs + nxt * 32 * BSTR;
            #pragma unroll
            for (int t = 0; t < 8; ++t) {
                int e = tid + 128 * t;
                int bk = e >> 5, c4 = e & 31;
                *reinterpret_cast<float4*>(Bn + bk * BSTR + 4 * c4) = pb[t];
            }
        }
        __syncthreads();
    }

    // Epilogue: scale by invS, write r
    #pragma unroll
    for (int r = 0; r < 4; ++r) {
        const int gi = i0 + 4 * ty + r;
        const float is = invS[4 * ty + r];
        float4 v = make_float4(acc[r][0] * is, acc[r][1] * is,
                               acc[r][2] * is, acc[r][3] * is);
        *reinterpret_cast<float4*>(out_r + ((size_t)b * L + gi) * D + d0 + 4 * tx) = v;
    }
}

// ---------------------------------------------------------------------------
extern "C" void kernel_launch(void* const* d_in, const int* in_sizes, int n_in,
                              void* d_out, int out_size) {
    const float* H = (const float*)d_in[0];
    const float* w = (const float*)d_in[1];

    float* out   = (float*)d_out;
    float* r     = out;            // first R_SIZE floats
    float* alpha = out + R_SIZE;   // next A_SIZE floats

    const int smem1 = (2 * 64 * SH2 + D2) * (int)sizeof(__half2);
    cudaFuncSetAttribute(scores_kernel,
                         cudaFuncAttributeMaxDynamicSharedMemorySize, smem1);

    const int smem2 = (16 * SSTR + 2 * 32 * BSTR + 16) * (int)sizeof(float);
    cudaFuncSetAttribute(fused_softmax_gemm,
                         cudaFuncAttributeMaxDynamicSharedMemorySize, smem2);

    scores_kernel<<<B * NPAIR, 512, smem1>>>(H, w);
    fused_softmax_gemm<<<dim3(2, L / 16, B), 128, smem2>>>(H, alpha, r);
}